// round 16
// baseline (speedup 1.0000x reference)
#include <cuda_runtime.h>
#include <cuda_bf16.h>
#include <cuda_fp16.h>
#include <stdint.h>

#define NHEAD 8
#define SLEN 2048
#define NSPLIT 2
#define SCALE 0.17677669529663689f
#define LOG2E 1.4426950408889634f
#define QSCALE (SCALE * LOG2E)

// ------------- device scratch (no allocation allowed) -------------
static __device__ __align__(16) __half g_Qh[NHEAD][SLEN][32];
static __device__ __align__(16) __half g_Kh[NHEAD][SLEN][32];
static __device__ __align__(16) __half g_Vth[NHEAD][32][SLEN];
static __device__ __align__(16) float g_G[NHEAD][SLEN][32];
static __device__ __align__(16) float g_Opart[NSPLIT][NHEAD][SLEN][32];
static __device__ __align__(16) float g_l[NSPLIT][NHEAD][SLEN];
// split-bf16 inputs for MMA projections
static __device__ __align__(16) __nv_bfloat16 g_Xqhi[SLEN * 256], g_Xqlo[SLEN * 256];
static __device__ __align__(16) __nv_bfloat16 g_Xkhi[SLEN * 256], g_Xklo[SLEN * 256];
static __device__ __align__(16) __nv_bfloat16 g_Wqthi[512 * 256], g_Wqtlo[512 * 256];
static __device__ __align__(16) __nv_bfloat16 g_Wkthi[512 * 256], g_Wktlo[512 * 256];
static __device__ __align__(16) __nv_bfloat16 g_Wothi[256 * 256], g_Wotlo[256 * 256];
static __device__ __align__(16) __nv_bfloat16 g_AOhi[SLEN * 256], g_AOlo[SLEN * 256];

// ------------- helpers -------------
__device__ __forceinline__ float ex2f(float x) {
    float y; asm("ex2.approx.f32 %0, %1;" : "=f"(y) : "f"(x)); return y;
}
__device__ __forceinline__ uint32_t packbf(float lo, float hi) {
    uint32_t r; asm("cvt.rn.bf16x2.f32 %0, %1, %2;" : "=r"(r) : "f"(hi), "f"(lo)); return r;
}
__device__ __forceinline__ uint32_t packh(float lo, float hi) {
    uint32_t r; asm("cvt.rn.f16x2.f32 %0, %1, %2;" : "=r"(r) : "f"(hi), "f"(lo)); return r;
}
__device__ __forceinline__ uint32_t h2ex2(uint32_t a) {
    uint32_t r; asm("ex2.approx.f16x2 %0, %1;" : "=r"(r) : "r"(a)); return r;
}
__device__ __forceinline__ void splitp(float x, float y, uint32_t &hi, uint32_t &lo) {
    hi = packbf(x, y);
    float xh = __uint_as_float(hi << 16);
    float yh = __uint_as_float(hi & 0xffff0000u);
    lo = packbf(x - xh, y - yh);
}
__device__ __forceinline__ void mma_bf16(float* d, const uint32_t* a, uint32_t b0, uint32_t b1) {
    asm volatile("mma.sync.aligned.m16n8k16.row.col.f32.bf16.bf16.f32 "
        "{%0,%1,%2,%3},{%4,%5,%6,%7},{%8,%9},{%0,%1,%2,%3};"
        : "+f"(d[0]), "+f"(d[1]), "+f"(d[2]), "+f"(d[3])
        : "r"(a[0]), "r"(a[1]), "r"(a[2]), "r"(a[3]), "r"(b0), "r"(b1));
}
__device__ __forceinline__ void mma_f16(float* d, const uint32_t* a, uint32_t b0, uint32_t b1) {
    asm volatile("mma.sync.aligned.m16n8k16.row.col.f32.f16.f16.f32 "
        "{%0,%1,%2,%3},{%4,%5,%6,%7},{%8,%9},{%0,%1,%2,%3};"
        : "+f"(d[0]), "+f"(d[1]), "+f"(d[2]), "+f"(d[3])
        : "r"(a[0]), "r"(a[1]), "r"(a[2]), "r"(a[3]), "r"(b0), "r"(b1));
}
__device__ __forceinline__ uint32_t smaddr(const void* p) {
    return (uint32_t)__cvta_generic_to_shared(p);
}
__device__ __forceinline__ void ldsm4(uint32_t* r, const void* p) {
    uint32_t a = smaddr(p);
    asm volatile("ldmatrix.sync.aligned.m8n8.x4.shared.b16 {%0,%1,%2,%3},[%4];"
        : "=r"(r[0]), "=r"(r[1]), "=r"(r[2]), "=r"(r[3]) : "r"(a));
}
__device__ __forceinline__ void cp_async16(uint32_t s, const void* g) {
    asm volatile("cp.async.cg.shared.global [%0], [%1], 16;" :: "r"(s), "l"(g));
}
__device__ __forceinline__ void cp_commit() { asm volatile("cp.async.commit_group;"); }
template<int N> __device__ __forceinline__ void cp_wait() {
    asm volatile("cp.async.wait_group %0;" :: "n"(N));
}
__device__ __forceinline__ void split_store(float v, __nv_bfloat16* hi, __nv_bfloat16* lo) {
    __nv_bfloat16 h = __float2bfloat16(v);
    *hi = h;
    *lo = __float2bfloat16(v - __bfloat162float(h));
}

// =============== kernel 0: split/transposed-split prepass ===============
__global__ __launch_bounds__(256) void split_kernel(
    const float* __restrict__ Xq, const float* __restrict__ Xkv,
    const float* __restrict__ Wq, const float* __restrict__ Wk,
    const float* __restrict__ Wo)
{
    const int NX = SLEN * 256;     // 524288
    const int NW = 256 * 512;      // 131072
    const int NO = 256 * 256;      // 65536
    int i = blockIdx.x * 256 + threadIdx.x;
    if (i < NX) {
        split_store(Xq[i], &g_Xqhi[i], &g_Xqlo[i]);
    } else if (i < 2 * NX) {
        int j = i - NX;
        split_store(Xkv[j], &g_Xkhi[j], &g_Xklo[j]);
    } else if (i < 2 * NX + NW) {
        int j = i - 2 * NX;                 // j = n*256 + k
        int n = j >> 8, k = j & 255;
        split_store(Wq[k * 512 + n], &g_Wqthi[j], &g_Wqtlo[j]);
    } else if (i < 2 * NX + 2 * NW) {
        int j = i - 2 * NX - NW;
        int n = j >> 8, k = j & 255;
        split_store(Wk[k * 512 + n], &g_Wkthi[j], &g_Wktlo[j]);
    } else {
        int j = i - 2 * NX - 2 * NW;
        if (j < NO) {
            int n = j >> 8, k = j & 255;
            split_store(Wo[k * 256 + n], &g_Wothi[j], &g_Wotlo[j]);
        }
    }
}

// =============== kernel 1: input projections (split-bf16 MMA) ===============
__global__ __launch_bounds__(128) void proj_mma(
    const float* __restrict__ Bq, const float* __restrict__ Bk)
{
    __shared__ __align__(16) __nv_bfloat16 Ah[2][64][40], Al[2][64][40];
    __shared__ __align__(16) __nv_bfloat16 Bh[2][64][40], Bl[2][64][40];
    const int z = blockIdx.z;
    const __nv_bfloat16* __restrict__ Xhi  = z ? g_Xkhi  : g_Xqhi;
    const __nv_bfloat16* __restrict__ Xlo  = z ? g_Xklo  : g_Xqlo;
    const __nv_bfloat16* __restrict__ Wthi = z ? g_Wkthi : g_Wqthi;
    const __nv_bfloat16* __restrict__ Wtlo = z ? g_Wktlo : g_Wqtlo;
    const float* __restrict__ Bv = z ? Bk : Bq;
    const int m0 = blockIdx.y * 64, n0 = blockIdx.x * 64;
    const int tid = threadIdx.x, wid = tid >> 5, ln = tid & 31;
    const int r0 = ln >> 2, c0 = (ln & 3) * 2;

    auto load_stage = [&](int s, int kt) {
#pragma unroll
        for (int p = 0; p < 2; p++) {
            int e = tid + p * 128, r = e >> 2, c = (e & 3) * 8;
            cp_async16(smaddr(&Ah[s][r][c]), &Xhi[(m0 + r) * 256 + kt + c]);
            cp_async16(smaddr(&Al[s][r][c]), &Xlo[(m0 + r) * 256 + kt + c]);
            cp_async16(smaddr(&Bh[s][r][c]), &Wthi[(n0 + r) * 256 + kt + c]);
            cp_async16(smaddr(&Bl[s][r][c]), &Wtlo[(n0 + r) * 256 + kt + c]);
        }
    };

    float s[8][4];
#pragma unroll
    for (int n = 0; n < 8; n++)
#pragma unroll
        for (int j = 0; j < 4; j++) s[n][j] = 0.0f;

    load_stage(0, 0); cp_commit();

    for (int it = 0; it < 8; it++) {
        const int buf = it & 1;
        cp_wait<0>();
        __syncthreads();
        if (it + 1 < 8) { load_stage(buf ^ 1, (it + 1) * 32); cp_commit(); }

#pragma unroll
        for (int kc = 0; kc < 2; kc++) {
            uint32_t ah[4], al[4];
            ah[0] = *(const uint32_t*)&Ah[buf][wid * 16 + r0][kc * 16 + c0];
            ah[1] = *(const uint32_t*)&Ah[buf][wid * 16 + r0 + 8][kc * 16 + c0];
            ah[2] = *(const uint32_t*)&Ah[buf][wid * 16 + r0][kc * 16 + c0 + 8];
            ah[3] = *(const uint32_t*)&Ah[buf][wid * 16 + r0 + 8][kc * 16 + c0 + 8];
            al[0] = *(const uint32_t*)&Al[buf][wid * 16 + r0][kc * 16 + c0];
            al[1] = *(const uint32_t*)&Al[buf][wid * 16 + r0 + 8][kc * 16 + c0];
            al[2] = *(const uint32_t*)&Al[buf][wid * 16 + r0][kc * 16 + c0 + 8];
            al[3] = *(const uint32_t*)&Al[buf][wid * 16 + r0 + 8][kc * 16 + c0 + 8];
#pragma unroll
            for (int n = 0; n < 8; n++) {
                uint32_t bh0 = *(const uint32_t*)&Bh[buf][n * 8 + r0][kc * 16 + c0];
                uint32_t bh1 = *(const uint32_t*)&Bh[buf][n * 8 + r0][kc * 16 + c0 + 8];
                uint32_t bl0 = *(const uint32_t*)&Bl[buf][n * 8 + r0][kc * 16 + c0];
                uint32_t bl1 = *(const uint32_t*)&Bl[buf][n * 8 + r0][kc * 16 + c0 + 8];
                mma_bf16(s[n], ah, bh0, bh1);
                mma_bf16(s[n], ah, bl0, bl1);
                mma_bf16(s[n], al, bh0, bh1);
            }
        }
    }

    // epilogue: write Q (fp16, scaled by SCALE*LOG2E), K (fp16), V (fp16, transposed), G (fp32)
#pragma unroll
    for (int n = 0; n < 8; n++) {
#pragma unroll
        for (int j = 0; j < 4; j++) {
            int row = m0 + wid * 16 + r0 + (j >> 1) * 8;
            int col = n0 + n * 8 + c0 + (j & 1);
            float x = s[n][j] + Bv[col];
            int h = col >> 6, cc = col & 63;
            if (z == 0) {
                if (cc < 32) {
                    g_Qh[h][row][cc] = __float2half(x * QSCALE);
                } else {
                    g_G[h][row][cc - 32] = 1.0f / (1.0f + __expf(-x));
                }
            } else {
                if (cc < 32) {
                    g_Kh[h][row][cc] = __float2half(x);
                } else {
                    g_Vth[h][cc - 32][row] = __float2half(x);
                }
            }
        }
    }
}

// =============== kernel 2: flash attention (fp16 MMA, fixed-max softmax, f16x2 ex2) ===============
// dynamic smem layout (bytes):
//   Kh: 2 stages x 64x40 half  @ 0       (10240)
//   Vh: 2 stages x 32x72 half  @ 10240   (9216)
//   Bias: 2 stages x 64x68 f32 @ 19456   (34816)   total = 54272
#define ATTN_SMEM 54272
__global__ __launch_bounds__(128, 4) void attn_kernel(const float* __restrict__ bias)
{
    extern __shared__ __align__(16) char dynsm[];
    __half (*KhS)[64][40] = (__half(*)[64][40])(dynsm);
    __half (*VhS)[32][72] = (__half(*)[32][72])(dynsm + 10240);
    float* biasS = (float*)(dynsm + 19456);
#define BIASS(s, r, c) biasS[((s) * 64 + (r)) * 68 + (c)]

    const int h = blockIdx.y;
    const int z = blockIdx.z;
    const int tid = threadIdx.x, wid = tid >> 5, ln = tid & 31;
    const int q0b = blockIdx.x * 64;
    const int q0 = q0b + wid * 16;
    const int r0 = ln >> 2, c0 = (ln & 3) * 2;
    const int lr8 = ln & 7, lm = ln >> 3;   // ldmatrix addressing
    const uint32_t ONES = 0x3C003C00u;       // fp16 {1.0, 1.0}

    // one commit group = KV(stage) + bias(stage) for one iteration
    auto load_stage_kvb = [&](int s, int kt) {
#pragma unroll
        for (int p = 0; p < 2; p++) {
            int e = tid + p * 128, r = e >> 2, c = (e & 3) * 8;
            cp_async16(smaddr(&KhS[s][r][c]), &g_Kh[h][kt + r][c]);
        }
#pragma unroll
        for (int p = 0; p < 2; p++) {
            int e = tid + p * 128, r = e >> 3, c = (e & 7) * 8;
            cp_async16(smaddr(&VhS[s][r][c]), &g_Vth[h][r][kt + c]);
        }
#pragma unroll
        for (int p = 0; p < 8; p++) {
            int e = tid + p * 128, r = e >> 4, seg = e & 15;
            cp_async16(smaddr(&BIASS(s, r, seg * 4)),
                       &bias[(size_t)(h * SLEN + q0b + r) * SLEN + kt + seg * 4]);
        }
        cp_commit();
    };

    // Q fragments (single fp16, pre-scaled to log2 domain), 2 k-chunks of 16
    uint32_t qh[2][4];
#pragma unroll
    for (int kc = 0; kc < 2; kc++) {
        qh[kc][0] = *(const uint32_t*)&g_Qh[h][q0 + r0][kc * 16 + c0];
        qh[kc][1] = *(const uint32_t*)&g_Qh[h][q0 + r0 + 8][kc * 16 + c0];
        qh[kc][2] = *(const uint32_t*)&g_Qh[h][q0 + r0][kc * 16 + c0 + 8];
        qh[kc][3] = *(const uint32_t*)&g_Qh[h][q0 + r0 + 8][kc * 16 + c0 + 8];
    }

    float o[4][4];
#pragma unroll
    for (int n = 0; n < 4; n++)
#pragma unroll
        for (int j = 0; j < 4; j++) o[n][j] = 0.0f;
    float lacc[4] = { 0.0f, 0.0f, 0.0f, 0.0f };   // row sums via ones-MMA

    const int NIT = SLEN / 64 / NSPLIT;   // 16
    const int kstep = NSPLIT * 64;
    load_stage_kvb(0, z * 64);
    load_stage_kvb(1, z * 64 + kstep);

    for (int it = 0; it < NIT; it++) {
        const int kt = it * kstep + z * 64;
        const int buf = it & 1;
        if (it + 1 < NIT) cp_wait<1>(); else cp_wait<0>();
        __syncthreads();

        // S(log2) = Q K^T  (Q pre-scaled by SCALE*LOG2E)
        float s[8][4];
#pragma unroll
        for (int n = 0; n < 8; n++) {
            s[n][0] = s[n][1] = s[n][2] = s[n][3] = 0.0f;
            uint32_t kh[4];
            ldsm4(kh, &KhS[buf][n * 8 + lr8][lm * 8]);
            mma_f16(s[n], qh[0], kh[0], kh[1]);
            mma_f16(s[n], qh[1], kh[2], kh[3]);
        }
        // add bias (log2 domain) in fp32
        const int br0 = wid * 16 + r0;
#pragma unroll
        for (int n = 0; n < 8; n++) {
            float2 b0 = *(const float2*)&BIASS(buf, br0, n * 8 + c0);
            float2 b1 = *(const float2*)&BIASS(buf, br0 + 8, n * 8 + c0);
            s[n][0] = fmaf(b0.x, LOG2E, s[n][0]);
            s[n][1] = fmaf(b0.y, LOG2E, s[n][1]);
            s[n][2] = fmaf(b1.x, LOG2E, s[n][2]);
            s[n][3] = fmaf(b1.y, LOG2E, s[n][3]);
        }
        // pack to f16x2 then dual-half ex2 -> P fragments directly
        uint32_t ph[4][4];
#pragma unroll
        for (int kc = 0; kc < 4; kc++) {
            ph[kc][0] = h2ex2(packh(s[2 * kc][0],     s[2 * kc][1]));
            ph[kc][1] = h2ex2(packh(s[2 * kc][2],     s[2 * kc][3]));
            ph[kc][2] = h2ex2(packh(s[2 * kc + 1][0], s[2 * kc + 1][1]));
            ph[kc][3] = h2ex2(packh(s[2 * kc + 1][2], s[2 * kc + 1][3]));
        }
        // row sums l += P @ ones  (exact fp32 accumulation, no shuffles needed)
#pragma unroll
        for (int kc = 0; kc < 4; kc++) {
            mma_f16(lacc, ph[kc], ONES, ONES);
        }
        // O += P V
#pragma unroll
        for (int n = 0; n < 4; n++) {
            uint32_t vh[8];
            ldsm4(vh,     &VhS[buf][n * 8 + lr8][lm * 8]);
            ldsm4(vh + 4, &VhS[buf][n * 8 + lr8][32 + lm * 8]);
#pragma unroll
            for (int kc = 0; kc < 4; kc++) {
                mma_f16(o[n], ph[kc], vh[kc * 2], vh[kc * 2 + 1]);
            }
        }

        __syncthreads();
        if (it + 2 < NIT) load_stage_kvb(buf, kt + 2 * kstep);
    }
#pragma unroll
    for (int n = 0; n < 4; n++) {
        float2 w0 = { o[n][0], o[n][1] };
        float2 w1 = { o[n][2], o[n][3] };
        *(float2*)&g_Opart[z][h][q0 + r0][n * 8 + c0] = w0;
        *(float2*)&g_Opart[z][h][q0 + r0 + 8][n * 8 + c0] = w1;
    }
    if ((ln & 3) == 0) {
        g_l[z][h][q0 + r0] = lacc[0];
        g_l[z][h][q0 + r0 + 8] = lacc[2];
    }
#undef BIASS
}

// =============== kernel 2b: split-K merge + gate -> AO (bf16 split), coalesced ===============
__global__ __launch_bounds__(256) void merge_kernel()
{
    int t = blockIdx.x * 256 + threadIdx.x;   // 131072 threads: 8 per (h,q) row
    int row = t >> 3, cs = (t & 7) * 4;
    int h = row >> 11, q = row & 2047;

    float rl = 1.0f / (g_l[0][h][q] + g_l[1][h][q]);

    float4 x0 = *(const float4*)&g_Opart[0][h][q][cs];
    float4 x1 = *(const float4*)&g_Opart[1][h][q][cs];
    float4 gg = *(const float4*)&g_G[h][q][cs];
    float4 r;
    r.x = (x0.x + x1.x) * rl * gg.x;
    r.y = (x0.y + x1.y) * rl * gg.y;
    r.z = (x0.z + x1.z) * rl * gg.z;
    r.w = (x0.w + x1.w) * rl * gg.w;
    uint32_t h01, l01, h23, l23;
    splitp(r.x, r.y, h01, l01);
    splitp(r.z, r.w, h23, l23);
    int base = q * 256 + h * 32 + cs;
    *(uint2*)&g_AOhi[base] = make_uint2(h01, h23);
    *(uint2*)&g_AOlo[base] = make_uint2(l01, l23);
}

// =============== kernel 3: output projection (split-bf16 MMA) ===============
__global__ __launch_bounds__(128) void outproj_mma(
    float* __restrict__ out, const float* __restrict__ Bv)
{
    __shared__ __align__(16) __nv_bfloat16 Ah[2][64][40], Al[2][64][40];
    __shared__ __align__(16) __nv_bfloat16 Bh[2][64][40], Bl[2][64][40];
    const int m0 = blockIdx.y * 64, n0 = blockIdx.x * 64;
    const int tid = threadIdx.x, wid = tid >> 5, ln = tid & 31;
    const int r0 = ln >> 2, c0 = (ln & 3) * 2;

    auto load_stage = [&](int s, int kt) {
#pragma unroll
        for (int p = 0; p < 2; p++) {
            int e = tid + p * 128, r = e >> 2, c = (e & 3) * 8;
            cp_async16(smaddr(&Ah[s][r][c]), &g_AOhi[(m0 + r) * 256 + kt + c]);
            cp_async16(smaddr(&Al[s][r][c]), &g_AOlo[(m0 + r) * 256 + kt + c]);
            cp_async16(smaddr(&Bh[s][r][c]), &g_Wothi[(n0 + r) * 256 + kt + c]);
            cp_async16(smaddr(&Bl[s][r][c]), &g_Wotlo[(n0 + r) * 256 + kt + c]);
        }
    };

    float s[8][4];
#pragma unroll
    for (int n = 0; n < 8; n++)
#pragma unroll
        for (int j = 0; j < 4; j++) s[n][j] = 0.0f;

    load_stage(0, 0); cp_commit();

    for (int it = 0; it < 8; it++) {
        const int buf = it & 1;
        cp_wait<0>();
        __syncthreads();
        if (it + 1 < 8) { load_stage(buf ^ 1, (it + 1) * 32); cp_commit(); }

#pragma unroll
        for (int kc = 0; kc < 2; kc++) {
            uint32_t ah[4], al[4];
            ah[0] = *(const uint32_t*)&Ah[buf][wid * 16 + r0][kc * 16 + c0];
            ah[1] = *(const uint32_t*)&Ah[buf][wid * 16 + r0 + 8][kc * 16 + c0];
            ah[2] = *(const uint32_t*)&Ah[buf][wid * 16 + r0][kc * 16 + c0 + 8];
            ah[3] = *(const uint32_t*)&Ah[buf][wid * 16 + r0 + 8][kc * 16 + c0 + 8];
            al[0] = *(const uint32_t*)&Al[buf][wid * 16 + r0][kc * 16 + c0];
            al[1] = *(const uint32_t*)&Al[buf][wid * 16 + r0 + 8][kc * 16 + c0];
            al[2] = *(const uint32_t*)&Al[buf][wid * 16 + r0][kc * 16 + c0 + 8];
            al[3] = *(const uint32_t*)&Al[buf][wid * 16 + r0 + 8][kc * 16 + c0 + 8];
#pragma unroll
            for (int n = 0; n < 8; n++) {
                uint32_t bh0 = *(const uint32_t*)&Bh[buf][n * 8 + r0][kc * 16 + c0];
                uint32_t bh1 = *(const uint32_t*)&Bh[buf][n * 8 + r0][kc * 16 + c0 + 8];
                uint32_t bl0 = *(const uint32_t*)&Bl[buf][n * 8 + r0][kc * 16 + c0];
                uint32_t bl1 = *(const uint32_t*)&Bl[buf][n * 8 + r0][kc * 16 + c0 + 8];
                mma_bf16(s[n], ah, bh0, bh1);
                mma_bf16(s[n], ah, bl0, bl1);
                mma_bf16(s[n], al, bh0, bh1);
            }
        }
    }

#pragma unroll
    for (int n = 0; n < 8; n++) {
#pragma unroll
        for (int half = 0; half < 2; half++) {
            int row = m0 + wid * 16 + r0 + half * 8;
            int col = n0 + n * 8 + c0;
            float2 v = { s[n][half * 2 + 0] + Bv[col], s[n][half * 2 + 1] + Bv[col + 1] };
            *(float2*)&out[row * 256 + col] = v;
        }
    }
}

// =============== launch ===============
extern "C" void kernel_launch(void* const* d_in, const int* in_sizes, int n_in,
                              void* d_out, int out_size) {
    const float* q_inputs   = (const float*)d_in[0];
    const float* kv_inputs  = (const float*)d_in[1];
    const float* bias       = (const float*)d_in[2];
    const float* qg_weights = (const float*)d_in[3];
    const float* kv_weights = (const float*)d_in[4];
    const float* qg_bias    = (const float*)d_in[5];
    const float* kv_bias    = (const float*)d_in[6];
    const float* o_weights  = (const float*)d_in[7];
    const float* o_bias     = (const float*)d_in[8];
    float* out = (float*)d_out;

    cudaFuncSetAttribute(attn_kernel, cudaFuncAttributeMaxDynamicSharedMemorySize, ATTN_SMEM);

    split_kernel<<<5376, 256>>>(q_inputs, kv_inputs, qg_weights, kv_weights, o_weights);
    proj_mma<<<dim3(8, 32, 2), 128>>>(qg_bias, kv_bias);
    attn_kernel<<<dim3(32, 8, NSPLIT), 128, ATTN_SMEM>>>(bias);
    merge_kernel<<<512, 256>>>();
    outproj_mma<<<dim3(4, 32), 128>>>(out, o_bias);
}

// round 17
// speedup vs baseline: 1.1251x; 1.1251x over previous
#include <cuda_runtime.h>
#include <cuda_bf16.h>
#include <cuda_fp16.h>
#include <stdint.h>

#define NHEAD 8
#define SLEN 2048
#define NSPLIT 2
#define SCALE 0.17677669529663689f
#define LOG2E 1.4426950408889634f
#define QSCALE (SCALE * LOG2E)

// ------------- device scratch (no allocation allowed) -------------
static __device__ __align__(16) __half g_Qh[NHEAD][SLEN][32];
static __device__ __align__(16) __half g_Kh[NHEAD][SLEN][32];
static __device__ __align__(16) __half g_Vth[NHEAD][32][SLEN];
static __device__ __align__(16) float g_G[NHEAD][SLEN][32];
static __device__ __align__(16) float g_Opart[NSPLIT][NHEAD][SLEN][32];
static __device__ __align__(16) float g_l[NSPLIT][NHEAD][SLEN];
// fp16 inputs for MMA projections (single precision term)
static __device__ __align__(16) __half g_Xqh[SLEN * 256];
static __device__ __align__(16) __half g_Xkh[SLEN * 256];
static __device__ __align__(16) __half g_Wqth[512 * 256];
static __device__ __align__(16) __half g_Wkth[512 * 256];
// outproj stays split-bf16 (output-facing precision)
static __device__ __align__(16) __nv_bfloat16 g_Wothi[256 * 256], g_Wotlo[256 * 256];
static __device__ __align__(16) __nv_bfloat16 g_AOhi[SLEN * 256], g_AOlo[SLEN * 256];

// ------------- helpers -------------
__device__ __forceinline__ float ex2f(float x) {
    float y; asm("ex2.approx.f32 %0, %1;" : "=f"(y) : "f"(x)); return y;
}
__device__ __forceinline__ uint32_t packbf(float lo, float hi) {
    uint32_t r; asm("cvt.rn.bf16x2.f32 %0, %1, %2;" : "=r"(r) : "f"(hi), "f"(lo)); return r;
}
__device__ __forceinline__ uint32_t packh(float lo, float hi) {
    uint32_t r; asm("cvt.rn.f16x2.f32 %0, %1, %2;" : "=r"(r) : "f"(hi), "f"(lo)); return r;
}
__device__ __forceinline__ void splitp(float x, float y, uint32_t &hi, uint32_t &lo) {
    hi = packbf(x, y);
    float xh = __uint_as_float(hi << 16);
    float yh = __uint_as_float(hi & 0xffff0000u);
    lo = packbf(x - xh, y - yh);
}
__device__ __forceinline__ void mma_bf16(float* d, const uint32_t* a, uint32_t b0, uint32_t b1) {
    asm volatile("mma.sync.aligned.m16n8k16.row.col.f32.bf16.bf16.f32 "
        "{%0,%1,%2,%3},{%4,%5,%6,%7},{%8,%9},{%0,%1,%2,%3};"
        : "+f"(d[0]), "+f"(d[1]), "+f"(d[2]), "+f"(d[3])
        : "r"(a[0]), "r"(a[1]), "r"(a[2]), "r"(a[3]), "r"(b0), "r"(b1));
}
__device__ __forceinline__ void mma_f16(float* d, const uint32_t* a, uint32_t b0, uint32_t b1) {
    asm volatile("mma.sync.aligned.m16n8k16.row.col.f32.f16.f16.f32 "
        "{%0,%1,%2,%3},{%4,%5,%6,%7},{%8,%9},{%0,%1,%2,%3};"
        : "+f"(d[0]), "+f"(d[1]), "+f"(d[2]), "+f"(d[3])
        : "r"(a[0]), "r"(a[1]), "r"(a[2]), "r"(a[3]), "r"(b0), "r"(b1));
}
__device__ __forceinline__ uint32_t smaddr(const void* p) {
    return (uint32_t)__cvta_generic_to_shared(p);
}
__device__ __forceinline__ void ldsm4(uint32_t* r, const void* p) {
    uint32_t a = smaddr(p);
    asm volatile("ldmatrix.sync.aligned.m8n8.x4.shared.b16 {%0,%1,%2,%3},[%4];"
        : "=r"(r[0]), "=r"(r[1]), "=r"(r[2]), "=r"(r[3]) : "r"(a));
}
__device__ __forceinline__ void cp_async16(uint32_t s, const void* g) {
    asm volatile("cp.async.cg.shared.global [%0], [%1], 16;" :: "r"(s), "l"(g));
}
__device__ __forceinline__ void cp_commit() { asm volatile("cp.async.commit_group;"); }
template<int N> __device__ __forceinline__ void cp_wait() {
    asm volatile("cp.async.wait_group %0;" :: "n"(N));
}
__device__ __forceinline__ void split_store(float v, __nv_bfloat16* hi, __nv_bfloat16* lo) {
    __nv_bfloat16 h = __float2bfloat16(v);
    *hi = h;
    *lo = __float2bfloat16(v - __bfloat162float(h));
}

// =============== kernel 0: convert/transpose prepass ===============
// X -> fp16 copy, Wq/Wk -> fp16 transpose, Wo -> split-bf16 transpose
__global__ __launch_bounds__(256) void split_kernel(
    const float* __restrict__ Xq, const float* __restrict__ Xkv,
    const float* __restrict__ Wq, const float* __restrict__ Wk,
    const float* __restrict__ Wo)
{
    const int NX = SLEN * 256;     // 524288
    const int NW = 256 * 512;      // 131072
    const int NO = 256 * 256;      // 65536
    int i = blockIdx.x * 256 + threadIdx.x;
    if (i < NX) {
        g_Xqh[i] = __float2half(Xq[i]);
    } else if (i < 2 * NX) {
        int j = i - NX;
        g_Xkh[j] = __float2half(Xkv[j]);
    } else if (i < 2 * NX + NW) {
        int j = i - 2 * NX;                 // j = n*256 + k
        int n = j >> 8, k = j & 255;
        g_Wqth[j] = __float2half(Wq[k * 512 + n]);
    } else if (i < 2 * NX + 2 * NW) {
        int j = i - 2 * NX - NW;
        int n = j >> 8, k = j & 255;
        g_Wkth[j] = __float2half(Wk[k * 512 + n]);
    } else {
        int j = i - 2 * NX - 2 * NW;
        if (j < NO) {
            int n = j >> 8, k = j & 255;
            split_store(Wo[k * 256 + n], &g_Wothi[j], &g_Wotlo[j]);
        }
    }
}

// =============== kernel 1: input projections (single-fp16 MMA) ===============
__global__ __launch_bounds__(128) void proj_mma(
    const float* __restrict__ Bq, const float* __restrict__ Bk)
{
    __shared__ __align__(16) __half Ah[2][64][40];
    __shared__ __align__(16) __half Bh[2][64][40];
    const int z = blockIdx.z;
    const __half* __restrict__ Xh  = z ? g_Xkh  : g_Xqh;
    const __half* __restrict__ Wth = z ? g_Wkth : g_Wqth;
    const float* __restrict__ Bv = z ? Bk : Bq;
    const int m0 = blockIdx.y * 64, n0 = blockIdx.x * 64;
    const int tid = threadIdx.x, wid = tid >> 5, ln = tid & 31;
    const int r0 = ln >> 2, c0 = (ln & 3) * 2;

    auto load_stage = [&](int s, int kt) {
#pragma unroll
        for (int p = 0; p < 2; p++) {
            int e = tid + p * 128, r = e >> 2, c = (e & 3) * 8;
            cp_async16(smaddr(&Ah[s][r][c]), &Xh[(m0 + r) * 256 + kt + c]);
            cp_async16(smaddr(&Bh[s][r][c]), &Wth[(n0 + r) * 256 + kt + c]);
        }
    };

    float s[8][4];
#pragma unroll
    for (int n = 0; n < 8; n++)
#pragma unroll
        for (int j = 0; j < 4; j++) s[n][j] = 0.0f;

    load_stage(0, 0); cp_commit();

    for (int it = 0; it < 8; it++) {
        const int buf = it & 1;
        cp_wait<0>();
        __syncthreads();
        if (it + 1 < 8) { load_stage(buf ^ 1, (it + 1) * 32); cp_commit(); }

#pragma unroll
        for (int kc = 0; kc < 2; kc++) {
            uint32_t ah[4];
            ah[0] = *(const uint32_t*)&Ah[buf][wid * 16 + r0][kc * 16 + c0];
            ah[1] = *(const uint32_t*)&Ah[buf][wid * 16 + r0 + 8][kc * 16 + c0];
            ah[2] = *(const uint32_t*)&Ah[buf][wid * 16 + r0][kc * 16 + c0 + 8];
            ah[3] = *(const uint32_t*)&Ah[buf][wid * 16 + r0 + 8][kc * 16 + c0 + 8];
#pragma unroll
            for (int n = 0; n < 8; n++) {
                uint32_t bh0 = *(const uint32_t*)&Bh[buf][n * 8 + r0][kc * 16 + c0];
                uint32_t bh1 = *(const uint32_t*)&Bh[buf][n * 8 + r0][kc * 16 + c0 + 8];
                mma_f16(s[n], ah, bh0, bh1);
            }
        }
    }

    // epilogue: write Q (fp16, scaled by SCALE*LOG2E), K (fp16), V (fp16, transposed), G (fp32)
#pragma unroll
    for (int n = 0; n < 8; n++) {
#pragma unroll
        for (int j = 0; j < 4; j++) {
            int row = m0 + wid * 16 + r0 + (j >> 1) * 8;
            int col = n0 + n * 8 + c0 + (j & 1);
            float x = s[n][j] + Bv[col];
            int h = col >> 6, cc = col & 63;
            if (z == 0) {
                if (cc < 32) {
                    g_Qh[h][row][cc] = __float2half(x * QSCALE);
                } else {
                    g_G[h][row][cc - 32] = 1.0f / (1.0f + __expf(-x));
                }
            } else {
                if (cc < 32) {
                    g_Kh[h][row][cc] = __float2half(x);
                } else {
                    g_Vth[h][cc - 32][row] = __float2half(x);
                }
            }
        }
    }
}

// =============== kernel 2: flash attention (fp16 MMA, fixed-max softmax) ===============
// dynamic smem layout (bytes):
//   Kh: 2 stages x 64x40 half  @ 0       (10240)
//   Vh: 2 stages x 32x72 half  @ 10240   (9216)
//   Bias: 2 stages x 64x68 f32 @ 19456   (34816)   total = 54272
#define ATTN_SMEM 54272
__global__ __launch_bounds__(128, 4) void attn_kernel(const float* __restrict__ bias)
{
    extern __shared__ __align__(16) char dynsm[];
    __half (*KhS)[64][40] = (__half(*)[64][40])(dynsm);
    __half (*VhS)[32][72] = (__half(*)[32][72])(dynsm + 10240);
    float* biasS = (float*)(dynsm + 19456);
#define BIASS(s, r, c) biasS[((s) * 64 + (r)) * 68 + (c)]

    const int h = blockIdx.y;
    const int z = blockIdx.z;
    const int tid = threadIdx.x, wid = tid >> 5, ln = tid & 31;
    const int q0b = blockIdx.x * 64;
    const int q0 = q0b + wid * 16;
    const int r0 = ln >> 2, c0 = (ln & 3) * 2;
    const int lr8 = ln & 7, lm = ln >> 3;   // ldmatrix addressing
    const uint32_t ONES = 0x3C003C00u;       // fp16 {1.0, 1.0}

    // one commit group = KV(stage) + bias(stage) for one iteration
    auto load_stage_kvb = [&](int s, int kt) {
#pragma unroll
        for (int p = 0; p < 2; p++) {
            int e = tid + p * 128, r = e >> 2, c = (e & 3) * 8;
            cp_async16(smaddr(&KhS[s][r][c]), &g_Kh[h][kt + r][c]);
        }
#pragma unroll
        for (int p = 0; p < 2; p++) {
            int e = tid + p * 128, r = e >> 3, c = (e & 7) * 8;
            cp_async16(smaddr(&VhS[s][r][c]), &g_Vth[h][r][kt + c]);
        }
#pragma unroll
        for (int p = 0; p < 8; p++) {
            int e = tid + p * 128, r = e >> 4, seg = e & 15;
            cp_async16(smaddr(&BIASS(s, r, seg * 4)),
                       &bias[(size_t)(h * SLEN + q0b + r) * SLEN + kt + seg * 4]);
        }
        cp_commit();
    };

    // Q fragments (single fp16, pre-scaled to log2 domain), 2 k-chunks of 16
    uint32_t qh[2][4];
#pragma unroll
    for (int kc = 0; kc < 2; kc++) {
        qh[kc][0] = *(const uint32_t*)&g_Qh[h][q0 + r0][kc * 16 + c0];
        qh[kc][1] = *(const uint32_t*)&g_Qh[h][q0 + r0 + 8][kc * 16 + c0];
        qh[kc][2] = *(const uint32_t*)&g_Qh[h][q0 + r0][kc * 16 + c0 + 8];
        qh[kc][3] = *(const uint32_t*)&g_Qh[h][q0 + r0 + 8][kc * 16 + c0 + 8];
    }

    float o[4][4];
#pragma unroll
    for (int n = 0; n < 4; n++)
#pragma unroll
        for (int j = 0; j < 4; j++) o[n][j] = 0.0f;
    float lacc[4] = { 0.0f, 0.0f, 0.0f, 0.0f };   // row sums via ones-MMA

    const int NIT = SLEN / 64 / NSPLIT;   // 16
    const int kstep = NSPLIT * 64;
    load_stage_kvb(0, z * 64);
    load_stage_kvb(1, z * 64 + kstep);

    for (int it = 0; it < NIT; it++) {
        const int kt = it * kstep + z * 64;
        const int buf = it & 1;
        if (it + 1 < NIT) cp_wait<1>(); else cp_wait<0>();
        __syncthreads();

        // S(log2) = Q K^T  (Q pre-scaled by SCALE*LOG2E)
        float s[8][4];
#pragma unroll
        for (int n = 0; n < 8; n++) {
            s[n][0] = s[n][1] = s[n][2] = s[n][3] = 0.0f;
            uint32_t kh[4];
            ldsm4(kh, &KhS[buf][n * 8 + lr8][lm * 8]);
            mma_f16(s[n], qh[0], kh[0], kh[1]);
            mma_f16(s[n], qh[1], kh[2], kh[3]);
        }
        // p = exp2(s + bias*LOG2E)  — fp32 ex2, fixed max
        const int br0 = wid * 16 + r0;
#pragma unroll
        for (int n = 0; n < 8; n++) {
            float2 b0 = *(const float2*)&BIASS(buf, br0, n * 8 + c0);
            float2 b1 = *(const float2*)&BIASS(buf, br0 + 8, n * 8 + c0);
            s[n][0] = ex2f(fmaf(b0.x, LOG2E, s[n][0]));
            s[n][1] = ex2f(fmaf(b0.y, LOG2E, s[n][1]));
            s[n][2] = ex2f(fmaf(b1.x, LOG2E, s[n][2]));
            s[n][3] = ex2f(fmaf(b1.y, LOG2E, s[n][3]));
        }
        // pack P into single fp16 A-fragments
        uint32_t ph[4][4];
#pragma unroll
        for (int kc = 0; kc < 4; kc++) {
            ph[kc][0] = packh(s[2 * kc][0],     s[2 * kc][1]);
            ph[kc][1] = packh(s[2 * kc][2],     s[2 * kc][3]);
            ph[kc][2] = packh(s[2 * kc + 1][0], s[2 * kc + 1][1]);
            ph[kc][3] = packh(s[2 * kc + 1][2], s[2 * kc + 1][3]);
        }
        // row sums l += P @ ones  (exact fp32 accumulation, no shuffles needed)
#pragma unroll
        for (int kc = 0; kc < 4; kc++) {
            mma_f16(lacc, ph[kc], ONES, ONES);
        }
        // O += P V
#pragma unroll
        for (int n = 0; n < 4; n++) {
            uint32_t vh[8];
            ldsm4(vh,     &VhS[buf][n * 8 + lr8][lm * 8]);
            ldsm4(vh + 4, &VhS[buf][n * 8 + lr8][32 + lm * 8]);
#pragma unroll
            for (int kc = 0; kc < 4; kc++) {
                mma_f16(o[n], ph[kc], vh[kc * 2], vh[kc * 2 + 1]);
            }
        }

        __syncthreads();
        if (it + 2 < NIT) load_stage_kvb(buf, kt + 2 * kstep);
    }
#pragma unroll
    for (int n = 0; n < 4; n++) {
        float2 w0 = { o[n][0], o[n][1] };
        float2 w1 = { o[n][2], o[n][3] };
        *(float2*)&g_Opart[z][h][q0 + r0][n * 8 + c0] = w0;
        *(float2*)&g_Opart[z][h][q0 + r0 + 8][n * 8 + c0] = w1;
    }
    if ((ln & 3) == 0) {
        g_l[z][h][q0 + r0] = lacc[0];
        g_l[z][h][q0 + r0 + 8] = lacc[2];
    }
#undef BIASS
}

// =============== kernel 2b: split-K merge + gate -> AO (bf16 split), coalesced ===============
__global__ __launch_bounds__(256) void merge_kernel()
{
    int t = blockIdx.x * 256 + threadIdx.x;   // 131072 threads: 8 per (h,q) row
    int row = t >> 3, cs = (t & 7) * 4;
    int h = row >> 11, q = row & 2047;

    float rl = 1.0f / (g_l[0][h][q] + g_l[1][h][q]);

    float4 x0 = *(const float4*)&g_Opart[0][h][q][cs];
    float4 x1 = *(const float4*)&g_Opart[1][h][q][cs];
    float4 gg = *(const float4*)&g_G[h][q][cs];
    float4 r;
    r.x = (x0.x + x1.x) * rl * gg.x;
    r.y = (x0.y + x1.y) * rl * gg.y;
    r.z = (x0.z + x1.z) * rl * gg.z;
    r.w = (x0.w + x1.w) * rl * gg.w;
    uint32_t h01, l01, h23, l23;
    splitp(r.x, r.y, h01, l01);
    splitp(r.z, r.w, h23, l23);
    int base = q * 256 + h * 32 + cs;
    *(uint2*)&g_AOhi[base] = make_uint2(h01, h23);
    *(uint2*)&g_AOlo[base] = make_uint2(l01, l23);
}

// =============== kernel 3: output projection (split-bf16 MMA) ===============
__global__ __launch_bounds__(128) void outproj_mma(
    float* __restrict__ out, const float* __restrict__ Bv)
{
    __shared__ __align__(16) __nv_bfloat16 Ah[2][64][40], Al[2][64][40];
    __shared__ __align__(16) __nv_bfloat16 Bh[2][64][40], Bl[2][64][40];
    const int m0 = blockIdx.y * 64, n0 = blockIdx.x * 64;
    const int tid = threadIdx.x, wid = tid >> 5, ln = tid & 31;
    const int r0 = ln >> 2, c0 = (ln & 3) * 2;

    auto load_stage = [&](int s, int kt) {
#pragma unroll
        for (int p = 0; p < 2; p++) {
            int e = tid + p * 128, r = e >> 2, c = (e & 3) * 8;
            cp_async16(smaddr(&Ah[s][r][c]), &g_AOhi[(m0 + r) * 256 + kt + c]);
            cp_async16(smaddr(&Al[s][r][c]), &g_AOlo[(m0 + r) * 256 + kt + c]);
            cp_async16(smaddr(&Bh[s][r][c]), &g_Wothi[(n0 + r) * 256 + kt + c]);
            cp_async16(smaddr(&Bl[s][r][c]), &g_Wotlo[(n0 + r) * 256 + kt + c]);
        }
    };

    float s[8][4];
#pragma unroll
    for (int n = 0; n < 8; n++)
#pragma unroll
        for (int j = 0; j < 4; j++) s[n][j] = 0.0f;

    load_stage(0, 0); cp_commit();

    for (int it = 0; it < 8; it++) {
        const int buf = it & 1;
        cp_wait<0>();
        __syncthreads();
        if (it + 1 < 8) { load_stage(buf ^ 1, (it + 1) * 32); cp_commit(); }

#pragma unroll
        for (int kc = 0; kc < 2; kc++) {
            uint32_t ah[4], al[4];
            ah[0] = *(const uint32_t*)&Ah[buf][wid * 16 + r0][kc * 16 + c0];
            ah[1] = *(const uint32_t*)&Ah[buf][wid * 16 + r0 + 8][kc * 16 + c0];
            ah[2] = *(const uint32_t*)&Ah[buf][wid * 16 + r0][kc * 16 + c0 + 8];
            ah[3] = *(const uint32_t*)&Ah[buf][wid * 16 + r0 + 8][kc * 16 + c0 + 8];
            al[0] = *(const uint32_t*)&Al[buf][wid * 16 + r0][kc * 16 + c0];
            al[1] = *(const uint32_t*)&Al[buf][wid * 16 + r0 + 8][kc * 16 + c0];
            al[2] = *(const uint32_t*)&Al[buf][wid * 16 + r0][kc * 16 + c0 + 8];
            al[3] = *(const uint32_t*)&Al[buf][wid * 16 + r0 + 8][kc * 16 + c0 + 8];
#pragma unroll
            for (int n = 0; n < 8; n++) {
                uint32_t bh0 = *(const uint32_t*)&Bh[buf][n * 8 + r0][kc * 16 + c0];
                uint32_t bh1 = *(const uint32_t*)&Bh[buf][n * 8 + r0][kc * 16 + c0 + 8];
                uint32_t bl0 = *(const uint32_t*)&Bl[buf][n * 8 + r0][kc * 16 + c0];
                uint32_t bl1 = *(const uint32_t*)&Bl[buf][n * 8 + r0][kc * 16 + c0 + 8];
                mma_bf16(s[n], ah, bh0, bh1);
                mma_bf16(s[n], ah, bl0, bl1);
                mma_bf16(s[n], al, bh0, bh1);
            }
        }
    }

#pragma unroll
    for (int n = 0; n < 8; n++) {
#pragma unroll
        for (int half = 0; half < 2; half++) {
            int row = m0 + wid * 16 + r0 + half * 8;
            int col = n0 + n * 8 + c0;
            float2 v = { s[n][half * 2 + 0] + Bv[col], s[n][half * 2 + 1] + Bv[col + 1] };
            *(float2*)&out[row * 256 + col] = v;
        }
    }
}

// =============== launch ===============
extern "C" void kernel_launch(void* const* d_in, const int* in_sizes, int n_in,
                              void* d_out, int out_size) {
    const float* q_inputs   = (const float*)d_in[0];
    const float* kv_inputs  = (const float*)d_in[1];
    const float* bias       = (const float*)d_in[2];
    const float* qg_weights = (const float*)d_in[3];
    const float* kv_weights = (const float*)d_in[4];
    const float* qg_bias    = (const float*)d_in[5];
    const float* kv_bias    = (const float*)d_in[6];
    const float* o_weights  = (const float*)d_in[7];
    const float* o_bias     = (const float*)d_in[8];
    float* out = (float*)d_out;

    cudaFuncSetAttribute(attn_kernel, cudaFuncAttributeMaxDynamicSharedMemorySize, ATTN_SMEM);

    split_kernel<<<5376, 256>>>(q_inputs, kv_inputs, qg_weights, kv_weights, o_weights);
    proj_mma<<<dim3(8, 32, 2), 128>>>(qg_bias, kv_bias);
    attn_kernel<<<dim3(32, 8, NSPLIT), 128, ATTN_SMEM>>>(bias);
    merge_kernel<<<512, 256>>>();
    outproj_mma<<<dim3(4, 32), 128>>>(out, o_bias);
}